// round 16
// baseline (speedup 1.0000x reference)
#include <cuda_runtime.h>
#include <cuda_fp16.h>
#include <cstdint>

#define NS 20000
#define NT 20000
#define NE 500000
#define DIN 128
#define HID 64
#define NH 3
#define HC 192
#define NALL (NS+NT)

#define OFF_XS  0
#define OFF_ATS (NS*HID)
#define OFF_XT  (OFF_ATS + NE*NH)
#define OFF_ATT (OFF_XT + NT*HID)

#define EDGE_BLOCKS ((NE + 255) / 256)
#define PREP_BLOCKS (((DIN*NH*2 + HC*NH*2 + 2*NH) * 32 + 255) / 256)

// ---------------- device scratch (static, no allocation) ----------------
__device__ __align__(16) __half g_H[NALL*HC];
__device__ __align__(16) float g_X1[NALL*HC];
__device__ __align__(16) float g_as[NALL*4];
__device__ __align__(16) float g_ad[NALL*4];
__device__ __align__(16) float g_V1s[DIN*NH];
__device__ __align__(16) float g_V1d[DIN*NH];
__device__ __align__(16) float g_V2s[HC*NH];
__device__ __align__(16) float g_V2d[HC*NH];
__device__ float g_ce[2*NH];

// CSR (nbr/eid split). cnt arrays zero on module load, re-zeroed trailing.
__device__ int g_cntT[NT];
__device__ int g_cntS[NS];
__device__ int g_offT[NT];
__device__ int g_offS[NS];
__device__ int g_curT[NT];
__device__ int g_curS[NS];
__device__ int g_nbrT[NE];
__device__ int g_eidT[NE];
__device__ int g_nbrS[NE];
__device__ int g_eidS[NE];
__device__ float g_eaT[NE];
__device__ float g_eaS[NE];

// ---------------- fused: edge histogram + prep ----------------
__global__ void hist_prep_kernel(const int* __restrict__ srcI, const int* __restrict__ dstI,
                                 const float* __restrict__ W1,
                                 const float* __restrict__ as1, const float* __restrict__ ad1,
                                 const float* __restrict__ Ws2, const float* __restrict__ Wd2,
                                 const float* __restrict__ as2, const float* __restrict__ ad2,
                                 const float* __restrict__ We1, const float* __restrict__ ae1,
                                 const float* __restrict__ We2, const float* __restrict__ ae2) {
    if (blockIdx.x < EDGE_BLOCKS) {
        int e = blockIdx.x * blockDim.x + threadIdx.x;
        if (e >= NE) return;
        atomicAdd(&g_cntT[__ldg(&dstI[e])], 1);
        atomicAdd(&g_cntS[__ldg(&srcI[e])], 1);
        return;
    }
    int w = ((blockIdx.x - EDGE_BLOCKS) * blockDim.x + threadIdx.x) >> 5;
    int lane = threadIdx.x & 31;
    const int nV1 = DIN*NH, nV2 = HC*NH;
    const float* Wm; const float* av; float* dstp; int k, h;
    if (w < nV1)                   { k = w/NH; h = w%NH; Wm = W1;  av = as1; dstp = &g_V1s[k*NH+h]; }
    else if ((w -= nV1) < nV1)     { k = w/NH; h = w%NH; Wm = W1;  av = ad1; dstp = &g_V1d[k*NH+h]; }
    else if ((w -= nV1) < nV2)     { k = w/NH; h = w%NH; Wm = Ws2; av = as2; dstp = &g_V2s[k*NH+h]; }
    else if ((w -= nV2) < nV2)     { k = w/NH; h = w%NH; Wm = Wd2; av = ad2; dstp = &g_V2d[k*NH+h]; }
    else if ((w -= nV2) < 2*NH)    { int layer = w/NH; h = w%NH; k = 0;
                                     Wm = layer ? We2 : We1; av = layer ? ae2 : ae1;
                                     dstp = &g_ce[layer*NH+h]; }
    else return;
    float s = Wm[k*HC + h*HID + lane] * av[h*HID + lane]
            + Wm[k*HC + h*HID + lane + 32] * av[h*HID + lane + 32];
    #pragma unroll
    for (int o = 16; o; o >>= 1) s += __shfl_xor_sync(0xffffffffu, s, o);
    if (lane == 0) *dstp = s;
}

// ---------------- CSR build ----------------
__global__ void scan_kernel() {
    int* cnt = blockIdx.x ? g_cntS : g_cntT;
    int* off = blockIdx.x ? g_offS : g_offT;
    int* cur = blockIdx.x ? g_curS : g_curT;
    const int n = blockIdx.x ? NS : NT;
    __shared__ int partial[1024];
    const int t = threadIdx.x;
    const int chunk = (n + 1023) / 1024;
    int start = t * chunk;
    int s = 0;
    for (int j = 0; j < chunk; j++) {
        int idx = start + j;
        if (idx < n) s += cnt[idx];
    }
    partial[t] = s;
    __syncthreads();
    for (int d = 1; d < 1024; d <<= 1) {
        int v = (t >= d) ? partial[t - d] : 0;
        __syncthreads();
        partial[t] += v;
        __syncthreads();
    }
    int run = partial[t] - s;
    for (int j = 0; j < chunk; j++) {
        int idx = start + j;
        if (idx < n) {
            off[idx] = run;
            cur[idx] = run;
            run += cnt[idx];
        }
    }
}

__global__ void fill_kernel(const int* __restrict__ srcI, const int* __restrict__ dstI,
                            const float* __restrict__ ea) {
    int e = blockIdx.x * blockDim.x + threadIdx.x;
    if (e >= NE) return;
    int u = __ldg(&srcI[e]);
    int v = __ldg(&dstI[e]);
    float w = __ldg(&ea[e]);
    int p1 = atomicAdd(&g_curT[v], 1);
    g_nbrT[p1] = u; g_eidT[p1] = e; g_eaT[p1] = w;
    int p2 = atomicAdd(&g_curS[u], 1);
    g_nbrS[p2] = v; g_eidS[p2] = e; g_eaS[p2] = w;
}

__global__ void zero_cnt_kernel() {
    int i = blockIdx.x * blockDim.x + threadIdx.x;
    if (i < NT) g_cntT[i] = 0;
    else if (i < NT + NS) g_cntS[i - NT] = 0;
}

// ---------------- fp16 tensor-core GEMM ----------------
__device__ __forceinline__ void ldsm_x4(uint32_t& r0, uint32_t& r1, uint32_t& r2, uint32_t& r3,
                                        uint32_t addr) {
    asm volatile("ldmatrix.sync.aligned.m8n8.x4.shared.b16 {%0,%1,%2,%3}, [%4];"
                 : "=r"(r0), "=r"(r1), "=r"(r2), "=r"(r3) : "r"(addr));
}
__device__ __forceinline__ void ldsm_x4t(uint32_t& r0, uint32_t& r1, uint32_t& r2, uint32_t& r3,
                                         uint32_t addr) {
    asm volatile("ldmatrix.sync.aligned.m8n8.x4.trans.shared.b16 {%0,%1,%2,%3}, [%4];"
                 : "=r"(r0), "=r"(r1), "=r"(r2), "=r"(r3) : "r"(addr));
}

template<int K, int KC>
__global__ void gemm_fp16_kernel(const float* __restrict__ X0, const float* __restrict__ X1,
                                 int M0, const float* __restrict__ W,
                                 __half* __restrict__ C, int M) {
    constexpr int AST = (KC == 128) ? 136 : 104;
    __shared__ __half As[64][AST];
    __shared__ __half Bs[KC][72];
    const int tid = threadIdx.x;
    const int warp = tid >> 5;
    const int lane = tid & 31;
    const int q = lane >> 2;
    const int m = lane & 3;
    const int rowBase = blockIdx.x * 64;
    const int colBase = blockIdx.y * 64;

    float c[8][4];
    #pragma unroll
    for (int i = 0; i < 8; i++)
        #pragma unroll
        for (int j = 0; j < 4; j++) c[i][j] = 0.f;

    const int l15 = lane & 15;
    const uint32_t aAddrBase = (uint32_t)__cvta_generic_to_shared(
        &As[warp*16 + l15][(lane < 16) ? 0 : 8]);
    const uint32_t bAddrBase = (uint32_t)__cvta_generic_to_shared(
        &Bs[l15][(lane < 16) ? 0 : 8]);

    for (int k0 = 0; k0 < K; k0 += KC) {
        #pragma unroll
        for (int i = 0; i < KC/8; i++) {
            int idx4 = tid + i*128;
            int row = idx4 / (KC/4);
            int c4 = (idx4 % (KC/4)) * 4;
            int gr = rowBase + row;
            float4 v = make_float4(0.f, 0.f, 0.f, 0.f);
            if (gr < M) {
                const float* xr = (gr < M0) ? X0 + (size_t)gr*K : X1 + (size_t)(gr - M0)*K;
                v = *reinterpret_cast<const float4*>(xr + k0 + c4);
            }
            *reinterpret_cast<__half2*>(&As[row][c4])   = __floats2half2_rn(v.x, v.y);
            *reinterpret_cast<__half2*>(&As[row][c4+2]) = __floats2half2_rn(v.z, v.w);
        }
        #pragma unroll
        for (int i = 0; i < KC/8; i++) {
            int idx4 = tid + i*128;
            int kk = idx4 >> 4;
            int c4 = (idx4 & 15) * 4;
            float4 v = *reinterpret_cast<const float4*>(&W[(size_t)(k0+kk)*HC + colBase + c4]);
            *reinterpret_cast<__half2*>(&Bs[kk][c4])   = __floats2half2_rn(v.x, v.y);
            *reinterpret_cast<__half2*>(&Bs[kk][c4+2]) = __floats2half2_rn(v.z, v.w);
        }
        __syncthreads();

        #pragma unroll
        for (int ks = 0; ks < KC; ks += 16) {
            uint32_t a0, a1, a2, a3;
            ldsm_x4(a0, a1, a2, a3, aAddrBase + (uint32_t)(ks * sizeof(__half)));
            #pragma unroll
            for (int np = 0; np < 4; np++) {
                uint32_t b00, b01, b10, b11;
                ldsm_x4t(b00, b01, b10, b11,
                         bAddrBase + (uint32_t)((ks * 72 + 16*np) * sizeof(__half)));
                asm volatile(
                    "mma.sync.aligned.m16n8k16.row.col.f32.f16.f16.f32 "
                    "{%0,%1,%2,%3}, {%4,%5,%6,%7}, {%8,%9}, {%0,%1,%2,%3};"
                    : "+f"(c[2*np][0]), "+f"(c[2*np][1]), "+f"(c[2*np][2]), "+f"(c[2*np][3])
                    : "r"(a0), "r"(a1), "r"(a2), "r"(a3), "r"(b00), "r"(b01));
                asm volatile(
                    "mma.sync.aligned.m16n8k16.row.col.f32.f16.f16.f32 "
                    "{%0,%1,%2,%3}, {%4,%5,%6,%7}, {%8,%9}, {%0,%1,%2,%3};"
                    : "+f"(c[2*np+1][0]), "+f"(c[2*np+1][1]), "+f"(c[2*np+1][2]), "+f"(c[2*np+1][3])
                    : "r"(a0), "r"(a1), "r"(a2), "r"(a3), "r"(b10), "r"(b11));
            }
        }
        __syncthreads();
    }

    int r0 = rowBase + warp*16 + q;
    #pragma unroll
    for (int nt = 0; nt < 8; nt++) {
        int col = colBase + nt*8 + 2*m;
        if (r0 < M)
            *reinterpret_cast<__half2*>(&C[(size_t)r0*HC + col]) = __floats2half2_rn(c[nt][0], c[nt][1]);
        if (r0 + 8 < M)
            *reinterpret_cast<__half2*>(&C[(size_t)(r0+8)*HC + col]) = __floats2half2_rn(c[nt][2], c[nt][3]);
    }
}

// ---------------- proj: persistent grid-stride, V vectors in registers ----------------
template<int K>
__global__ void proj_kernel(const float* __restrict__ X0, const float* __restrict__ X1, int M0,
                            const float* __restrict__ Vs, const float* __restrict__ Vd,
                            float* __restrict__ as_o, float* __restrict__ ad_o, int M) {
    constexpr int NI = (K/4 + 31) / 32;
    const int lane = threadIdx.x & 31;
    const int gw = (blockIdx.x * blockDim.x + threadIdx.x) >> 5;
    const int nW = (gridDim.x * blockDim.x) >> 5;

    float vs0[NI][4], vs1[NI][4], vs2[NI][4], vd0[NI][4], vd1[NI][4], vd2[NI][4];
    #pragma unroll
    for (int ni = 0; ni < NI; ni++) {
        int i4 = lane + 32*ni;
        #pragma unroll
        for (int c = 0; c < 4; c++) {
            int k = i4*4 + c;
            bool ok = (i4 < K/4);
            vs0[ni][c] = ok ? __ldg(&Vs[k*NH+0]) : 0.f;
            vs1[ni][c] = ok ? __ldg(&Vs[k*NH+1]) : 0.f;
            vs2[ni][c] = ok ? __ldg(&Vs[k*NH+2]) : 0.f;
            vd0[ni][c] = ok ? __ldg(&Vd[k*NH+0]) : 0.f;
            vd1[ni][c] = ok ? __ldg(&Vd[k*NH+1]) : 0.f;
            vd2[ni][c] = ok ? __ldg(&Vd[k*NH+2]) : 0.f;
        }
    }

    for (int n = gw; n < M; n += nW) {
        const float* X = (n < M0) ? X0 + (size_t)n*K : X1 + (size_t)(n - M0)*K;
        const float4* X4 = reinterpret_cast<const float4*>(X);
        float s0=0.f,s1=0.f,s2=0.f,d0=0.f,d1=0.f,d2=0.f;
        #pragma unroll
        for (int ni = 0; ni < NI; ni++) {
            int i4 = lane + 32*ni;
            if (i4 < K/4) {
                float4 xv = __ldg(&X4[i4]);
                s0 += xv.x*vs0[ni][0] + xv.y*vs0[ni][1] + xv.z*vs0[ni][2] + xv.w*vs0[ni][3];
                s1 += xv.x*vs1[ni][0] + xv.y*vs1[ni][1] + xv.z*vs1[ni][2] + xv.w*vs1[ni][3];
                s2 += xv.x*vs2[ni][0] + xv.y*vs2[ni][1] + xv.z*vs2[ni][2] + xv.w*vs2[ni][3];
                d0 += xv.x*vd0[ni][0] + xv.y*vd0[ni][1] + xv.z*vd0[ni][2] + xv.w*vd0[ni][3];
                d1 += xv.x*vd1[ni][0] + xv.y*vd1[ni][1] + xv.z*vd1[ni][2] + xv.w*vd1[ni][3];
                d2 += xv.x*vd2[ni][0] + xv.y*vd2[ni][1] + xv.z*vd2[ni][2] + xv.w*vd2[ni][3];
            }
        }
        #pragma unroll
        for (int o = 16; o; o >>= 1) {
            s0 += __shfl_xor_sync(0xffffffffu, s0, o);
            s1 += __shfl_xor_sync(0xffffffffu, s1, o);
            s2 += __shfl_xor_sync(0xffffffffu, s2, o);
            d0 += __shfl_xor_sync(0xffffffffu, d0, o);
            d1 += __shfl_xor_sync(0xffffffffu, d1, o);
            d2 += __shfl_xor_sync(0xffffffffu, d2, o);
        }
        if (lane == 0) {
            as_o[n*4+0] = s0; as_o[n*4+1] = s1; as_o[n*4+2] = s2;
            ad_o[n*4+0] = d0; ad_o[n*4+1] = d1; ad_o[n*4+2] = d2;
        }
    }
}

// ---------------- fused aggregation: register exp, receiver-side head select ----------------
// warp per node; lane (<24) owns 8 cols (head = lane/8). Chunk c holds edges c*32+lane.
#define NCH 4   // deg <= 128 fast path (Poisson(25); fallback below covers the rest)
template<bool CONCAT>
__global__ void agg_kernel(const int* __restrict__ off, const int* __restrict__ cnt,
                           const int* __restrict__ nbrA, const int* __restrict__ eidA,
                           const float* __restrict__ eaA,
                           const float* __restrict__ asrc, const float* __restrict__ adst,
                           int layer,
                           const __half* __restrict__ Hval,
                           const float* __restrict__ bias,
                           const float* __restrict__ g, const float* __restrict__ be,
                           float* __restrict__ out, float* __restrict__ alpha_out, int M) {
    int n = (blockIdx.x * blockDim.x + threadIdx.x) >> 5;
    int lane = threadIdx.x & 31;
    if (n >= M) return;

    const int r0 = __ldg(&off[n]);
    const int deg = __ldg(&cnt[n]);
    const float ce0 = g_ce[layer*NH+0], ce1 = g_ce[layer*NH+1], ce2 = g_ce[layer*NH+2];
    float4 adv = __ldg(reinterpret_cast<const float4*>(&adst[4*n]));
    const float ad0 = adv.x, ad1 = adv.y, ad2 = adv.z;

    // pass 1: logits -> exp kept in registers (chunked, all 3 heads) + denominators
    float P0[NCH], P1[NCH], P2[NCH];
    float s0 = 0.f, s1 = 0.f, s2 = 0.f;
    #pragma unroll
    for (int c = 0; c < NCH; c++) {
        int j = c*32 + lane;
        float p0 = 0.f, p1 = 0.f, p2 = 0.f;
        if (j < deg) {
            int idx = r0 + j;
            int u = __ldg(&nbrA[idx]);
            float w = __ldg(&eaA[idx]);
            float4 av = __ldg(reinterpret_cast<const float4*>(&asrc[4*u]));
            float l0 = av.x + ad0 + ce0*w;
            float l1 = av.y + ad1 + ce1*w;
            float l2 = av.z + ad2 + ce2*w;
            l0 = l0 > 0.f ? l0 : 0.2f*l0;
            l1 = l1 > 0.f ? l1 : 0.2f*l1;
            l2 = l2 > 0.f ? l2 : 0.2f*l2;
            p0 = __expf(l0); p1 = __expf(l1); p2 = __expf(l2);
        }
        P0[c] = p0; P1[c] = p1; P2[c] = p2;
        s0 += p0; s1 += p1; s2 += p2;
    }
    // overflow tail (deg > 128): denominators only
    for (int j = NCH*32 + lane; j < deg; j += 32) {
        int idx = r0 + j;
        int u = __ldg(&nbrA[idx]);
        float w = __ldg(&eaA[idx]);
        float4 av = __ldg(reinterpret_cast<const float4*>(&asrc[4*u]));
        float l0 = av.x + ad0 + ce0*w;
        float l1 = av.y + ad1 + ce1*w;
        float l2 = av.z + ad2 + ce2*w;
        l0 = l0 > 0.f ? l0 : 0.2f*l0;
        l1 = l1 > 0.f ? l1 : 0.2f*l1;
        l2 = l2 > 0.f ? l2 : 0.2f*l2;
        s0 += __expf(l0); s1 += __expf(l1); s2 += __expf(l2);
    }
    #pragma unroll
    for (int o = 16; o; o >>= 1) {
        s0 += __shfl_xor_sync(0xffffffffu, s0, o);
        s1 += __shfl_xor_sync(0xffffffffu, s1, o);
        s2 += __shfl_xor_sync(0xffffffffu, s2, o);
    }
    const int hsel = (lane >> 3) > 2 ? 2 : (lane >> 3);
    const float invsel = (hsel == 0) ? 1.f/(s0 + 1e-16f)
                       : (hsel == 1) ? 1.f/(s1 + 1e-16f)
                                     : 1.f/(s2 + 1e-16f);
    const float adsel = (hsel == 0) ? ad0 : (hsel == 1) ? ad1 : ad2;
    const float cesel = (hsel == 0) ? ce0 : (hsel == 1) ? ce1 : ce2;
    __syncwarp();

    // pass 2: per edge: LDG.32 nbr + 3x SHFL (receiver-side head select) + LDG.128 gather
    const uint4* base = reinterpret_cast<const uint4*>(Hval);
    const bool act = lane < 24;
    float acc[8] = {0.f,0.f,0.f,0.f,0.f,0.f,0.f,0.f};
    #pragma unroll
    for (int c = 0; c < NCH; c++) {
        if (c*32 >= deg) break;
        const int jEnd = min(deg - c*32, 32);
        const float p0c = P0[c], p1c = P1[c], p2c = P2[c];
        #pragma unroll 8
        for (int jj = 0; jj < jEnd; jj++) {
            int idx = r0 + c*32 + jj;
            int u = __ldg(&nbrA[idx]);
            // shuffle edge jj's three head-exps from lane jj; select with MY head
            float v0 = __shfl_sync(0xffffffffu, p0c, jj);
            float v1 = __shfl_sync(0xffffffffu, p1c, jj);
            float v2 = __shfl_sync(0xffffffffu, p2c, jj);
            float wv = ((hsel == 0) ? v0 : (hsel == 1) ? v1 : v2) * invsel;
            if (act) {
                if (!CONCAT && (lane & 7) == 0) {
                    int e = __ldg(&eidA[idx]);
                    alpha_out[(size_t)e*NH + hsel] = wv;
                }
                uint4 hv = __ldg(&base[(size_t)u*24 + lane]);
                float2 f0 = __half22float2(*reinterpret_cast<__half2*>(&hv.x));
                float2 f1 = __half22float2(*reinterpret_cast<__half2*>(&hv.y));
                float2 f2 = __half22float2(*reinterpret_cast<__half2*>(&hv.z));
                float2 f3 = __half22float2(*reinterpret_cast<__half2*>(&hv.w));
                acc[0] += wv*f0.x; acc[1] += wv*f0.y;
                acc[2] += wv*f1.x; acc[3] += wv*f1.y;
                acc[4] += wv*f2.x; acc[5] += wv*f2.y;
                acc[6] += wv*f3.x; acc[7] += wv*f3.y;
            }
        }
    }
    // overflow tail (deg > 128): recompute exp inline
    for (int j = NCH*32; j < deg; j++) {
        int idx = r0 + j;
        int u = __ldg(&nbrA[idx]);
        float we = __ldg(&eaA[idx]);
        if (act) {
            float4 av = __ldg(reinterpret_cast<const float4*>(&asrc[4*u]));
            float avsel = (hsel == 0) ? av.x : (hsel == 1) ? av.y : av.z;
            float l = avsel + adsel + cesel*we;
            l = l > 0.f ? l : 0.2f*l;
            float wv = __expf(l) * invsel;
            if (!CONCAT && (lane & 7) == 0) {
                int e = __ldg(&eidA[idx]);
                alpha_out[(size_t)e*NH + hsel] = wv;
            }
            uint4 hv = __ldg(&base[(size_t)u*24 + lane]);
            float2 f0 = __half22float2(*reinterpret_cast<__half2*>(&hv.x));
            float2 f1 = __half22float2(*reinterpret_cast<__half2*>(&hv.y));
            float2 f2 = __half22float2(*reinterpret_cast<__half2*>(&hv.z));
            float2 f3 = __half22float2(*reinterpret_cast<__half2*>(&hv.w));
            acc[0] += wv*f0.x; acc[1] += wv*f0.y;
            acc[2] += wv*f1.x; acc[3] += wv*f1.y;
            acc[4] += wv*f2.x; acc[5] += wv*f2.y;
            acc[6] += wv*f3.x; acc[7] += wv*f3.y;
        }
    }

    if (CONCAT) {
        float v[8]; float sum = 0.f;
        if (act) {
            const float4* b4 = reinterpret_cast<const float4*>(bias);
            float4 bA = __ldg(&b4[2*lane]);
            float4 bB = __ldg(&b4[2*lane+1]);
            v[0]=acc[0]+bA.x; v[1]=acc[1]+bA.y; v[2]=acc[2]+bA.z; v[3]=acc[3]+bA.w;
            v[4]=acc[4]+bB.x; v[5]=acc[5]+bB.y; v[6]=acc[6]+bB.z; v[7]=acc[7]+bB.w;
            #pragma unroll
            for (int i = 0; i < 8; i++) {
                v[i] = v[i] > 0.f ? v[i] : 0.01f*v[i];
                sum += v[i];
            }
        }
        #pragma unroll
        for (int o = 16; o; o >>= 1) sum += __shfl_xor_sync(0xffffffffu, sum, o);
        float mean = sum * (1.f/HC);
        float var = 0.f;
        if (act) {
            #pragma unroll
            for (int i = 0; i < 8; i++) { float d = v[i] - mean; var += d*d; }
        }
        #pragma unroll
        for (int o = 16; o; o >>= 1) var += __shfl_xor_sync(0xffffffffu, var, o);
        float rstd = rsqrtf(var * (1.f/HC) + 1e-5f);
        if (act) {
            const float4* g4 = reinterpret_cast<const float4*>(g);
            const float4* e4 = reinterpret_cast<const float4*>(be);
            float4 gA = __ldg(&g4[2*lane]),   eA = __ldg(&e4[2*lane]);
            float4 gB = __ldg(&g4[2*lane+1]), eB = __ldg(&e4[2*lane+1]);
            float4* out4 = reinterpret_cast<float4*>(out) + (size_t)n * 48;
            float4 rA, rB;
            rA.x = (v[0]-mean)*rstd*gA.x + eA.x;
            rA.y = (v[1]-mean)*rstd*gA.y + eA.y;
            rA.z = (v[2]-mean)*rstd*gA.z + eA.z;
            rA.w = (v[3]-mean)*rstd*gA.w + eA.w;
            rB.x = (v[4]-mean)*rstd*gB.x + eB.x;
            rB.y = (v[5]-mean)*rstd*gB.y + eB.y;
            rB.z = (v[6]-mean)*rstd*gB.z + eB.z;
            rB.w = (v[7]-mean)*rstd*gB.w + eB.w;
            out4[2*lane]   = rA;
            out4[2*lane+1] = rB;
        }
    } else {
        float v[8]; float sum = 0.f;
        const bool own = lane < 8;
        #pragma unroll
        for (int i = 0; i < 8; i++) {
            float h1 = __shfl_down_sync(0xffffffffu, acc[i], 8);
            float h2 = __shfl_down_sync(0xffffffffu, acc[i], 16);
            v[i] = (acc[i] + h1 + h2) * (1.f/3.f);
        }
        if (own) {
            const float4* b4 = reinterpret_cast<const float4*>(bias);
            float4 bA = __ldg(&b4[2*lane]);
            float4 bB = __ldg(&b4[2*lane+1]);
            v[0]+=bA.x; v[1]+=bA.y; v[2]+=bA.z; v[3]+=bA.w;
            v[4]+=bB.x; v[5]+=bB.y; v[6]+=bB.z; v[7]+=bB.w;
            #pragma unroll
            for (int i = 0; i < 8; i++) {
                v[i] = v[i] > 0.f ? v[i] : 0.01f*v[i];
                sum += v[i];
            }
        } else sum = 0.f;
        #pragma unroll
        for (int o = 16; o; o >>= 1) sum += __shfl_xor_sync(0xffffffffu, sum, o);
        float mean = sum * (1.f/HID);
        float var = 0.f;
        if (own) {
            #pragma unroll
            for (int i = 0; i < 8; i++) { float d = v[i] - mean; var += d*d; }
        }
        #pragma unroll
        for (int o = 16; o; o >>= 1) var += __shfl_xor_sync(0xffffffffu, var, o);
        float rstd = rsqrtf(var * (1.f/HID) + 1e-5f);
        if (own) {
            const float4* g4 = reinterpret_cast<const float4*>(g);
            const float4* e4 = reinterpret_cast<const float4*>(be);
            float4 gA = __ldg(&g4[2*lane]),   eA = __ldg(&e4[2*lane]);
            float4 gB = __ldg(&g4[2*lane+1]), eB = __ldg(&e4[2*lane+1]);
            float4 rA, rB;
            rA.x = (v[0]-mean)*rstd*gA.x + eA.x;
            rA.y = (v[1]-mean)*rstd*gA.y + eA.y;
            rA.z = (v[2]-mean)*rstd*gA.z + eA.z;
            rA.w = (v[3]-mean)*rstd*gA.w + eA.w;
            rB.x = (v[4]-mean)*rstd*gB.x + eB.x;
            rB.y = (v[5]-mean)*rstd*gB.y + eB.y;
            rB.z = (v[6]-mean)*rstd*gB.z + eB.z;
            rB.w = (v[7]-mean)*rstd*gB.w + eB.w;
            float4* out4 = reinterpret_cast<float4*>(out) + (size_t)n * 16;
            out4[2*lane]   = rA;
            out4[2*lane+1] = rB;
        }
    }
}

// ---------------- host (single stream) ----------------
extern "C" void kernel_launch(void* const* d_in, const int* in_sizes, int n_in,
                              void* d_out, int out_size) {
    const float* x_s  = (const float*)d_in[0];
    const float* x_t  = (const float*)d_in[1];
    const int*   ei   = (const int*)  d_in[2];
    const float* ea   = (const float*)d_in[3];
    const float* W1   = (const float*)d_in[4];
    const float* a_s1 = (const float*)d_in[5];
    const float* a_d1 = (const float*)d_in[6];
    const float* We1  = (const float*)d_in[7];
    const float* a_e1 = (const float*)d_in[8];
    const float* b1   = (const float*)d_in[9];
    const float* Ws2  = (const float*)d_in[10];
    const float* Wd2  = (const float*)d_in[11];
    const float* a_s2 = (const float*)d_in[12];
    const float* a_d2 = (const float*)d_in[13];
    const float* We2  = (const float*)d_in[14];
    const float* a_e2 = (const float*)d_in[15];
    const float* b2   = (const float*)d_in[16];
    const float* g0   = (const float*)d_in[17];
    const float* be0  = (const float*)d_in[18];
    const float* g1   = (const float*)d_in[19];
    const float* be1  = (const float*)d_in[20];
    float* out = (float*)d_out;

    const int* srcI = ei;
    const int* dstI = ei + NE;

    __half *pH;
    float *pX1, *pAs, *pAd, *pV1s, *pV1d, *pV2s, *pV2d, *pEaT, *pEaS;
    int *pCntT, *pCntS, *pOffT, *pOffS, *pNbrT, *pEidT, *pNbrS, *pEidS;
    cudaGetSymbolAddress((void**)&pH,   g_H);
    cudaGetSymbolAddress((void**)&pX1,  g_X1);
    cudaGetSymbolAddress((void**)&pAs,  g_as);
    cudaGetSymbolAddress((void**)&pAd,  g_ad);
    cudaGetSymbolAddress((void**)&pV1s, g_V1s);
    cudaGetSymbolAddress((void**)&pV1d, g_V1d);
    cudaGetSymbolAddress((void**)&pV2s, g_V2s);
    cudaGetSymbolAddress((void**)&pV2d, g_V2d);
    cudaGetSymbolAddress((void**)&pCntT, g_cntT);
    cudaGetSymbolAddress((void**)&pCntS, g_cntS);
    cudaGetSymbolAddress((void**)&pOffT, g_offT);
    cudaGetSymbolAddress((void**)&pOffS, g_offS);
    cudaGetSymbolAddress((void**)&pNbrT, g_nbrT);
    cudaGetSymbolAddress((void**)&pEidT, g_eidT);
    cudaGetSymbolAddress((void**)&pNbrS, g_nbrS);
    cudaGetSymbolAddress((void**)&pEidS, g_eidS);
    cudaGetSymbolAddress((void**)&pEaT, g_eaT);
    cudaGetSymbolAddress((void**)&pEaS, g_eaS);

    __half* pHs = pH;
    __half* pHt = pH + (size_t)NS*HC;
    float* pX1t = pX1 + (size_t)NS*HC;

    const dim3 gemmGrid((NALL + 63) / 64, 3);
    const int nodeWarpBlocks = (NS * 32 + 255) / 256;
    const int projBlocks = 592;
    const int zeroBlocks = (NT + NS + 255) / 256;

    hist_prep_kernel<<<EDGE_BLOCKS + PREP_BLOCKS, 256>>>(srcI, dstI,
        W1, a_s1, a_d1, Ws2, Wd2, a_s2, a_d2, We1, a_e1, We2, a_e2);
    scan_kernel<<<2, 1024>>>();
    fill_kernel<<<EDGE_BLOCKS, 256>>>(srcI, dstI, ea);
    gemm_fp16_kernel<DIN, DIN><<<gemmGrid, 128>>>(x_s, x_t, NS, W1, pH, NALL);
    proj_kernel<DIN><<<projBlocks, 256>>>(x_s, x_t, NS, pV1s, pV1d, pAs, pAd, NALL);

    agg_kernel<true><<<nodeWarpBlocks, 256>>>(pOffT, pCntT, pNbrT, pEidT, pEaT,
                                              pAs, pAd + (size_t)NS*4, 0, pHs,
                                              b1, g0, be0, pX1t, nullptr, NT);
    agg_kernel<true><<<nodeWarpBlocks, 256>>>(pOffS, pCntS, pNbrS, pEidS, pEaS,
                                              pAs + (size_t)NS*4, pAd, 0, pHt,
                                              b1, g0, be0, pX1, nullptr, NS);

    gemm_fp16_kernel<HC, 96><<<gemmGrid, 128>>>(pX1, pX1t, NALL, Ws2, pH, NALL);
    proj_kernel<HC><<<projBlocks, 256>>>(pX1, pX1t, NALL, pV2s, pV2d, pAs, pAd, NALL);

    agg_kernel<false><<<nodeWarpBlocks, 256>>>(pOffT, pCntT, pNbrT, pEidT, pEaT,
                                               pAs, pAd + (size_t)NS*4, 1, pHs,
                                               b2, g1, be1, out + OFF_XT, out + OFF_ATT, NT);
    agg_kernel<false><<<nodeWarpBlocks, 256>>>(pOffS, pCntS, pNbrS, pEidS, pEaS,
                                               pAs + (size_t)NS*4, pAd, 1, pHt,
                                               b2, g1, be1, out + OFF_XS, out + OFF_ATS, NS);

    zero_cnt_kernel<<<zeroBlocks, 256>>>();
}

// round 17
// speedup vs baseline: 1.1263x; 1.1263x over previous
#include <cuda_runtime.h>
#include <cuda_fp16.h>
#include <cstdint>

#define NS 20000
#define NT 20000
#define NE 500000
#define DIN 128
#define HID 64
#define NH 3
#define HC 192
#define NALL (NS+NT)

#define OFF_XS  0
#define OFF_ATS (NS*HID)
#define OFF_XT  (OFF_ATS + NE*NH)
#define OFF_ATT (OFF_XT + NT*HID)

#define EDGE_BLOCKS ((NE + 255) / 256)
#define PREP_BLOCKS (((DIN*NH*2 + HC*NH*2 + 2*NH) * 32 + 255) / 256)

// ---------------- device scratch (static, no allocation) ----------------
__device__ __align__(16) __half g_H[NALL*HC];   // fp16 hidden states (s rows, then t rows)
__device__ __align__(16) float g_X1[NALL*HC];   // post-LN layer1 outputs (s rows, then t rows)
__device__ __align__(16) float g_P[3*NE];       // exp buffers, planar by head, CSR position
__device__ __align__(16) float g_as[NALL*4];    // src-role logit parts, stride 4
__device__ __align__(16) float g_ad[NALL*4];    // dst-role logit parts, stride 4
__device__ __align__(16) float g_V1s[DIN*NH];
__device__ __align__(16) float g_V1d[DIN*NH];
__device__ __align__(16) float g_V2s[HC*NH];
__device__ __align__(16) float g_V2d[HC*NH];
__device__ float g_ce[2*NH];

// CSR (nbr/eid split). cnt arrays are zero on module load and re-zeroed by
// zero_cnt_kernel at the END of every launch (deterministic invariant).
__device__ int g_cntT[NT];
__device__ int g_cntS[NS];
__device__ int g_offT[NT];
__device__ int g_offS[NS];
__device__ int g_curT[NT];
__device__ int g_curS[NS];
__device__ int g_nbrT[NE];
__device__ int g_eidT[NE];
__device__ int g_nbrS[NE];
__device__ int g_eidS[NE];
__device__ float g_eaT[NE];
__device__ float g_eaS[NE];

// ---------------- fused: edge histogram + prep ----------------
__global__ void hist_prep_kernel(const int* __restrict__ srcI, const int* __restrict__ dstI,
                                 const float* __restrict__ W1,
                                 const float* __restrict__ as1, const float* __restrict__ ad1,
                                 const float* __restrict__ Ws2, const float* __restrict__ Wd2,
                                 const float* __restrict__ as2, const float* __restrict__ ad2,
                                 const float* __restrict__ We1, const float* __restrict__ ae1,
                                 const float* __restrict__ We2, const float* __restrict__ ae2) {
    if (blockIdx.x < EDGE_BLOCKS) {
        int e = blockIdx.x * blockDim.x + threadIdx.x;
        if (e >= NE) return;
        atomicAdd(&g_cntT[__ldg(&dstI[e])], 1);
        atomicAdd(&g_cntS[__ldg(&srcI[e])], 1);
        return;
    }
    int w = ((blockIdx.x - EDGE_BLOCKS) * blockDim.x + threadIdx.x) >> 5;
    int lane = threadIdx.x & 31;
    const int nV1 = DIN*NH, nV2 = HC*NH;
    const float* Wm; const float* av; float* dstp; int k, h;
    if (w < nV1)                   { k = w/NH; h = w%NH; Wm = W1;  av = as1; dstp = &g_V1s[k*NH+h]; }
    else if ((w -= nV1) < nV1)     { k = w/NH; h = w%NH; Wm = W1;  av = ad1; dstp = &g_V1d[k*NH+h]; }
    else if ((w -= nV1) < nV2)     { k = w/NH; h = w%NH; Wm = Ws2; av = as2; dstp = &g_V2s[k*NH+h]; }
    else if ((w -= nV2) < nV2)     { k = w/NH; h = w%NH; Wm = Wd2; av = ad2; dstp = &g_V2d[k*NH+h]; }
    else if ((w -= nV2) < 2*NH)    { int layer = w/NH; h = w%NH; k = 0;
                                     Wm = layer ? We2 : We1; av = layer ? ae2 : ae1;
                                     dstp = &g_ce[layer*NH+h]; }
    else return;
    float s = Wm[k*HC + h*HID + lane] * av[h*HID + lane]
            + Wm[k*HC + h*HID + lane + 32] * av[h*HID + lane + 32];
    #pragma unroll
    for (int o = 16; o; o >>= 1) s += __shfl_xor_sync(0xffffffffu, s, o);
    if (lane == 0) *dstp = s;
}

// ---------------- CSR build ----------------
__global__ void scan_kernel() {
    int* cnt = blockIdx.x ? g_cntS : g_cntT;
    int* off = blockIdx.x ? g_offS : g_offT;
    int* cur = blockIdx.x ? g_curS : g_curT;
    const int n = blockIdx.x ? NS : NT;
    __shared__ int partial[1024];
    const int t = threadIdx.x;
    const int chunk = (n + 1023) / 1024;
    int start = t * chunk;
    int s = 0;
    for (int j = 0; j < chunk; j++) {
        int idx = start + j;
        if (idx < n) s += cnt[idx];
    }
    partial[t] = s;
    __syncthreads();
    for (int d = 1; d < 1024; d <<= 1) {
        int v = (t >= d) ? partial[t - d] : 0;
        __syncthreads();
        partial[t] += v;
        __syncthreads();
    }
    int run = partial[t] - s;
    for (int j = 0; j < chunk; j++) {
        int idx = start + j;
        if (idx < n) {
            off[idx] = run;
            cur[idx] = run;
            run += cnt[idx];
        }
    }
}

__global__ void fill_kernel(const int* __restrict__ srcI, const int* __restrict__ dstI,
                            const float* __restrict__ ea) {
    int e = blockIdx.x * blockDim.x + threadIdx.x;
    if (e >= NE) return;
    int u = __ldg(&srcI[e]);
    int v = __ldg(&dstI[e]);
    float w = __ldg(&ea[e]);
    int p1 = atomicAdd(&g_curT[v], 1);
    g_nbrT[p1] = u; g_eidT[p1] = e; g_eaT[p1] = w;
    int p2 = atomicAdd(&g_curS[u], 1);
    g_nbrS[p2] = v; g_eidS[p2] = e; g_eaS[p2] = w;
}

__global__ void zero_cnt_kernel() {
    int i = blockIdx.x * blockDim.x + threadIdx.x;
    if (i < NT) g_cntT[i] = 0;
    else if (i < NT + NS) g_cntS[i - NT] = 0;
}

// ---------------- fp16 tensor-core GEMM, single smem slab per K-chunk ----------------
__device__ __forceinline__ void ldsm_x4(uint32_t& r0, uint32_t& r1, uint32_t& r2, uint32_t& r3,
                                        uint32_t addr) {
    asm volatile("ldmatrix.sync.aligned.m8n8.x4.shared.b16 {%0,%1,%2,%3}, [%4];"
                 : "=r"(r0), "=r"(r1), "=r"(r2), "=r"(r3) : "r"(addr));
}
__device__ __forceinline__ void ldsm_x4t(uint32_t& r0, uint32_t& r1, uint32_t& r2, uint32_t& r3,
                                         uint32_t addr) {
    asm volatile("ldmatrix.sync.aligned.m8n8.x4.trans.shared.b16 {%0,%1,%2,%3}, [%4];"
                 : "=r"(r0), "=r"(r1), "=r"(r2), "=r"(r3) : "r"(addr));
}

template<int K, int KC>
__global__ void gemm_fp16_kernel(const float* __restrict__ X0, const float* __restrict__ X1,
                                 int M0, const float* __restrict__ W,
                                 __half* __restrict__ C, int M) {
    constexpr int AST = (KC == 128) ? 136 : 104;
    __shared__ __half As[64][AST];
    __shared__ __half Bs[KC][72];
    const int tid = threadIdx.x;
    const int warp = tid >> 5;
    const int lane = tid & 31;
    const int q = lane >> 2;
    const int m = lane & 3;
    const int rowBase = blockIdx.x * 64;
    const int colBase = blockIdx.y * 64;

    float c[8][4];
    #pragma unroll
    for (int i = 0; i < 8; i++)
        #pragma unroll
        for (int j = 0; j < 4; j++) c[i][j] = 0.f;

    const int l15 = lane & 15;
    const uint32_t aAddrBase = (uint32_t)__cvta_generic_to_shared(
        &As[warp*16 + l15][(lane < 16) ? 0 : 8]);
    const uint32_t bAddrBase = (uint32_t)__cvta_generic_to_shared(
        &Bs[l15][(lane < 16) ? 0 : 8]);

    for (int k0 = 0; k0 < K; k0 += KC) {
        #pragma unroll
        for (int i = 0; i < KC/8; i++) {
            int idx4 = tid + i*128;
            int row = idx4 / (KC/4);
            int c4 = (idx4 % (KC/4)) * 4;
            int gr = rowBase + row;
            float4 v = make_float4(0.f, 0.f, 0.f, 0.f);
            if (gr < M) {
                const float* xr = (gr < M0) ? X0 + (size_t)gr*K : X1 + (size_t)(gr - M0)*K;
                v = *reinterpret_cast<const float4*>(xr + k0 + c4);
            }
            *reinterpret_cast<__half2*>(&As[row][c4])   = __floats2half2_rn(v.x, v.y);
            *reinterpret_cast<__half2*>(&As[row][c4+2]) = __floats2half2_rn(v.z, v.w);
        }
        #pragma unroll
        for (int i = 0; i < KC/8; i++) {
            int idx4 = tid + i*128;
            int kk = idx4 >> 4;
            int c4 = (idx4 & 15) * 4;
            float4 v = *reinterpret_cast<const float4*>(&W[(size_t)(k0+kk)*HC + colBase + c4]);
            *reinterpret_cast<__half2*>(&Bs[kk][c4])   = __floats2half2_rn(v.x, v.y);
            *reinterpret_cast<__half2*>(&Bs[kk][c4+2]) = __floats2half2_rn(v.z, v.w);
        }
        __syncthreads();

        #pragma unroll
        for (int ks = 0; ks < KC; ks += 16) {
            uint32_t a0, a1, a2, a3;
            ldsm_x4(a0, a1, a2, a3, aAddrBase + (uint32_t)(ks * sizeof(__half)));
            #pragma unroll
            for (int np = 0; np < 4; np++) {
                uint32_t b00, b01, b10, b11;
                ldsm_x4t(b00, b01, b10, b11,
                         bAddrBase + (uint32_t)((ks * 72 + 16*np) * sizeof(__half)));
                asm volatile(
                    "mma.sync.aligned.m16n8k16.row.col.f32.f16.f16.f32 "
                    "{%0,%1,%2,%3}, {%4,%5,%6,%7}, {%8,%9}, {%0,%1,%2,%3};"
                    : "+f"(c[2*np][0]), "+f"(c[2*np][1]), "+f"(c[2*np][2]), "+f"(c[2*np][3])
                    : "r"(a0), "r"(a1), "r"(a2), "r"(a3), "r"(b00), "r"(b01));
                asm volatile(
                    "mma.sync.aligned.m16n8k16.row.col.f32.f16.f16.f32 "
                    "{%0,%1,%2,%3}, {%4,%5,%6,%7}, {%8,%9}, {%0,%1,%2,%3};"
                    : "+f"(c[2*np+1][0]), "+f"(c[2*np+1][1]), "+f"(c[2*np+1][2]), "+f"(c[2*np+1][3])
                    : "r"(a0), "r"(a1), "r"(a2), "r"(a3), "r"(b10), "r"(b11));
            }
        }
        __syncthreads();
    }

    int r0 = rowBase + warp*16 + q;
    #pragma unroll
    for (int nt = 0; nt < 8; nt++) {
        int col = colBase + nt*8 + 2*m;
        if (r0 < M)
            *reinterpret_cast<__half2*>(&C[(size_t)r0*HC + col]) = __floats2half2_rn(c[nt][0], c[nt][1]);
        if (r0 + 8 < M)
            *reinterpret_cast<__half2*>(&C[(size_t)(r0+8)*HC + col]) = __floats2half2_rn(c[nt][2], c[nt][3]);
    }
}

// ---------------- proj: persistent grid-stride, V vectors in registers ----------------
template<int K>
__global__ void proj_kernel(const float* __restrict__ X0, const float* __restrict__ X1, int M0,
                            const float* __restrict__ Vs, const float* __restrict__ Vd,
                            float* __restrict__ as_o, float* __restrict__ ad_o, int M) {
    constexpr int NI = (K/4 + 31) / 32;
    const int lane = threadIdx.x & 31;
    const int gw = (blockIdx.x * blockDim.x + threadIdx.x) >> 5;
    const int nW = (gridDim.x * blockDim.x) >> 5;

    float vs0[NI][4], vs1[NI][4], vs2[NI][4], vd0[NI][4], vd1[NI][4], vd2[NI][4];
    #pragma unroll
    for (int ni = 0; ni < NI; ni++) {
        int i4 = lane + 32*ni;
        #pragma unroll
        for (int c = 0; c < 4; c++) {
            int k = i4*4 + c;
            bool ok = (i4 < K/4);
            vs0[ni][c] = ok ? __ldg(&Vs[k*NH+0]) : 0.f;
            vs1[ni][c] = ok ? __ldg(&Vs[k*NH+1]) : 0.f;
            vs2[ni][c] = ok ? __ldg(&Vs[k*NH+2]) : 0.f;
            vd0[ni][c] = ok ? __ldg(&Vd[k*NH+0]) : 0.f;
            vd1[ni][c] = ok ? __ldg(&Vd[k*NH+1]) : 0.f;
            vd2[ni][c] = ok ? __ldg(&Vd[k*NH+2]) : 0.f;
        }
    }

    for (int n = gw; n < M; n += nW) {
        const float* X = (n < M0) ? X0 + (size_t)n*K : X1 + (size_t)(n - M0)*K;
        const float4* X4 = reinterpret_cast<const float4*>(X);
        float s0=0.f,s1=0.f,s2=0.f,d0=0.f,d1=0.f,d2=0.f;
        #pragma unroll
        for (int ni = 0; ni < NI; ni++) {
            int i4 = lane + 32*ni;
            if (i4 < K/4) {
                float4 xv = __ldg(&X4[i4]);
                s0 += xv.x*vs0[ni][0] + xv.y*vs0[ni][1] + xv.z*vs0[ni][2] + xv.w*vs0[ni][3];
                s1 += xv.x*vs1[ni][0] + xv.y*vs1[ni][1] + xv.z*vs1[ni][2] + xv.w*vs1[ni][3];
                s2 += xv.x*vs2[ni][0] + xv.y*vs2[ni][1] + xv.z*vs2[ni][2] + xv.w*vs2[ni][3];
                d0 += xv.x*vd0[ni][0] + xv.y*vd0[ni][1] + xv.z*vd0[ni][2] + xv.w*vd0[ni][3];
                d1 += xv.x*vd1[ni][0] + xv.y*vd1[ni][1] + xv.z*vd1[ni][2] + xv.w*vd1[ni][3];
                d2 += xv.x*vd2[ni][0] + xv.y*vd2[ni][1] + xv.z*vd2[ni][2] + xv.w*vd2[ni][3];
            }
        }
        #pragma unroll
        for (int o = 16; o; o >>= 1) {
            s0 += __shfl_xor_sync(0xffffffffu, s0, o);
            s1 += __shfl_xor_sync(0xffffffffu, s1, o);
            s2 += __shfl_xor_sync(0xffffffffu, s2, o);
            d0 += __shfl_xor_sync(0xffffffffu, d0, o);
            d1 += __shfl_xor_sync(0xffffffffu, d1, o);
            d2 += __shfl_xor_sync(0xffffffffu, d2, o);
        }
        if (lane == 0) {
            as_o[n*4+0] = s0; as_o[n*4+1] = s1; as_o[n*4+2] = s2;
            ad_o[n*4+0] = d0; ad_o[n*4+1] = d1; ad_o[n*4+2] = d2;
        }
    }
}

// ---------------- fused aggregation: logits + softmax + fp16 gather + LN ----------------
template<bool CONCAT>
__global__ void agg_kernel(const int* __restrict__ off, const int* __restrict__ cnt,
                           const int* __restrict__ nbrA, const int* __restrict__ eidA,
                           const float* __restrict__ eaA,
                           const float* __restrict__ asrc, const float* __restrict__ adst,
                           int layer,
                           const __half* __restrict__ Hval, float* __restrict__ P,
                           const float* __restrict__ bias,
                           const float* __restrict__ g, const float* __restrict__ be,
                           float* __restrict__ out, float* __restrict__ alpha_out, int M) {
    int n = (blockIdx.x * blockDim.x + threadIdx.x) >> 5;
    int lane = threadIdx.x & 31;
    if (n >= M) return;

    const int r0 = __ldg(&off[n]);
    const int deg = __ldg(&cnt[n]);
    const float ce0 = g_ce[layer*NH+0], ce1 = g_ce[layer*NH+1], ce2 = g_ce[layer*NH+2];
    float4 adv = __ldg(reinterpret_cast<const float4*>(&adst[4*n]));
    const float ad0 = adv.x, ad1 = adv.y, ad2 = adv.z;

    // pass 1: logits -> exp (planar by head, CSR position) + denominators
    float s0 = 0.f, s1 = 0.f, s2 = 0.f;
    for (int j = lane; j < deg; j += 32) {
        int idx = r0 + j;
        int u = __ldg(&nbrA[idx]);
        float w = __ldg(&eaA[idx]);
        float4 av = __ldg(reinterpret_cast<const float4*>(&asrc[4*u]));
        float l0 = av.x + ad0 + ce0*w;
        float l1 = av.y + ad1 + ce1*w;
        float l2 = av.z + ad2 + ce2*w;
        l0 = l0 > 0.f ? l0 : 0.2f*l0;
        l1 = l1 > 0.f ? l1 : 0.2f*l1;
        l2 = l2 > 0.f ? l2 : 0.2f*l2;
        float p0 = __expf(l0), p1 = __expf(l1), p2 = __expf(l2);
        P[idx] = p0; P[NE + idx] = p1; P[2*NE + idx] = p2;
        s0 += p0; s1 += p1; s2 += p2;
    }
    #pragma unroll
    for (int o = 16; o; o >>= 1) {
        s0 += __shfl_xor_sync(0xffffffffu, s0, o);
        s1 += __shfl_xor_sync(0xffffffffu, s1, o);
        s2 += __shfl_xor_sync(0xffffffffu, s2, o);
    }
    const int hsel = (lane >> 3) > 2 ? 2 : (lane >> 3);
    const float invsel = (hsel == 0) ? 1.f/(s0 + 1e-16f)
                       : (hsel == 1) ? 1.f/(s1 + 1e-16f)
                                     : 1.f/(s2 + 1e-16f);
    const float* Pl = P + (size_t)hsel * NE;
    __syncwarp();

    // pass 2: per edge: LDG.32 nbr + LDG.32 weight + LDG.128 gather (+pred. eid in layer2)
    const uint4* base = reinterpret_cast<const uint4*>(Hval);
    const bool act = lane < 24;
    float acc[8] = {0.f,0.f,0.f,0.f,0.f,0.f,0.f,0.f};
    #pragma unroll 8
    for (int j = 0; j < deg; j++) {
        int idx = r0 + j;
        int u = __ldg(&nbrA[idx]);
        if (act) {
            float w = __ldg(&Pl[idx]) * invsel;
            if (!CONCAT && (lane & 7) == 0) {
                int e = __ldg(&eidA[idx]);
                alpha_out[(size_t)e*NH + hsel] = w;
            }
            uint4 hv = __ldg(&base[(size_t)u*24 + lane]);
            float2 f0 = __half22float2(*reinterpret_cast<__half2*>(&hv.x));
            float2 f1 = __half22float2(*reinterpret_cast<__half2*>(&hv.y));
            float2 f2 = __half22float2(*reinterpret_cast<__half2*>(&hv.z));
            float2 f3 = __half22float2(*reinterpret_cast<__half2*>(&hv.w));
            acc[0] += w*f0.x; acc[1] += w*f0.y;
            acc[2] += w*f1.x; acc[3] += w*f1.y;
            acc[4] += w*f2.x; acc[5] += w*f2.y;
            acc[6] += w*f3.x; acc[7] += w*f3.y;
        }
    }

    if (CONCAT) {
        float v[8]; float sum = 0.f;
        if (act) {
            const float4* b4 = reinterpret_cast<const float4*>(bias);
            float4 bA = __ldg(&b4[2*lane]);
            float4 bB = __ldg(&b4[2*lane+1]);
            v[0]=acc[0]+bA.x; v[1]=acc[1]+bA.y; v[2]=acc[2]+bA.z; v[3]=acc[3]+bA.w;
            v[4]=acc[4]+bB.x; v[5]=acc[5]+bB.y; v[6]=acc[6]+bB.z; v[7]=acc[7]+bB.w;
            #pragma unroll
            for (int i = 0; i < 8; i++) {
                v[i] = v[i] > 0.f ? v[i] : 0.01f*v[i];
                sum += v[i];
            }
        }
        #pragma unroll
        for (int o = 16; o; o >>= 1) sum += __shfl_xor_sync(0xffffffffu, sum, o);
        float mean = sum * (1.f/HC);
        float var = 0.f;
        if (act) {
            #pragma unroll
            for (int i = 0; i < 8; i++) { float d = v[i] - mean; var += d*d; }
        }
        #pragma unroll
        for (int o = 16; o; o >>= 1) var += __shfl_xor_sync(0xffffffffu, var, o);
        float rstd = rsqrtf(var * (1.f/HC) + 1e-5f);
        if (act) {
            const float4* g4 = reinterpret_cast<const float4*>(g);
            const float4* e4 = reinterpret_cast<const float4*>(be);
            float4 gA = __ldg(&g4[2*lane]),   eA = __ldg(&e4[2*lane]);
            float4 gB = __ldg(&g4[2*lane+1]), eB = __ldg(&e4[2*lane+1]);
            float4* out4 = reinterpret_cast<float4*>(out) + (size_t)n * 48;
            float4 rA, rB;
            rA.x = (v[0]-mean)*rstd*gA.x + eA.x;
            rA.y = (v[1]-mean)*rstd*gA.y + eA.y;
            rA.z = (v[2]-mean)*rstd*gA.z + eA.z;
            rA.w = (v[3]-mean)*rstd*gA.w + eA.w;
            rB.x = (v[4]-mean)*rstd*gB.x + eB.x;
            rB.y = (v[5]-mean)*rstd*gB.y + eB.y;
            rB.z = (v[6]-mean)*rstd*gB.z + eB.z;
            rB.w = (v[7]-mean)*rstd*gB.w + eB.w;
            out4[2*lane]   = rA;
            out4[2*lane+1] = rB;
        }
    } else {
        float v[8]; float sum = 0.f;
        const bool own = lane < 8;
        #pragma unroll
        for (int i = 0; i < 8; i++) {
            float h1 = __shfl_down_sync(0xffffffffu, acc[i], 8);
            float h2 = __shfl_down_sync(0xffffffffu, acc[i], 16);
            v[i] = (acc[i] + h1 + h2) * (1.f/3.f);
        }
        if (own) {
            const float4* b4 = reinterpret_cast<const float4*>(bias);
            float4 bA = __ldg(&b4[2*lane]);
            float4 bB = __ldg(&b4[2*lane+1]);
            v[0]+=bA.x; v[1]+=bA.y; v[2]+=bA.z; v[3]+=bA.w;
            v[4]+=bB.x; v[5]+=bB.y; v[6]+=bB.z; v[7]+=bB.w;
            #pragma unroll
            for (int i = 0; i < 8; i++) {
                v[i] = v[i] > 0.f ? v[i] : 0.01f*v[i];
                sum += v[i];
            }
        } else sum = 0.f;
        #pragma unroll
        for (int o = 16; o; o >>= 1) sum += __shfl_xor_sync(0xffffffffu, sum, o);
        float mean = sum * (1.f/HID);
        float var = 0.f;
        if (own) {
            #pragma unroll
            for (int i = 0; i < 8; i++) { float d = v[i] - mean; var += d*d; }
        }
        #pragma unroll
        for (int o = 16; o; o >>= 1) var += __shfl_xor_sync(0xffffffffu, var, o);
        float rstd = rsqrtf(var * (1.f/HID) + 1e-5f);
        if (own) {
            const float4* g4 = reinterpret_cast<const float4*>(g);
            const float4* e4 = reinterpret_cast<const float4*>(be);
            float4 gA = __ldg(&g4[2*lane]),   eA = __ldg(&e4[2*lane]);
            float4 gB = __ldg(&g4[2*lane+1]), eB = __ldg(&e4[2*lane+1]);
            float4 rA, rB;
            rA.x = (v[0]-mean)*rstd*gA.x + eA.x;
            rA.y = (v[1]-mean)*rstd*gA.y + eA.y;
            rA.z = (v[2]-mean)*rstd*gA.z + eA.z;
            rA.w = (v[3]-mean)*rstd*gA.w + eA.w;
            rB.x = (v[4]-mean)*rstd*gB.x + eB.x;
            rB.y = (v[5]-mean)*rstd*gB.y + eB.y;
            rB.z = (v[6]-mean)*rstd*gB.z + eB.z;
            rB.w = (v[7]-mean)*rstd*gB.w + eB.w;
            float4* out4 = reinterpret_cast<float4*>(out) + (size_t)n * 16;
            out4[2*lane]   = rA;
            out4[2*lane+1] = rB;
        }
    }
}

// ---------------- host (single stream) ----------------
extern "C" void kernel_launch(void* const* d_in, const int* in_sizes, int n_in,
                              void* d_out, int out_size) {
    const float* x_s  = (const float*)d_in[0];
    const float* x_t  = (const float*)d_in[1];
    const int*   ei   = (const int*)  d_in[2];
    const float* ea   = (const float*)d_in[3];
    const float* W1   = (const float*)d_in[4];
    const float* a_s1 = (const float*)d_in[5];
    const float* a_d1 = (const float*)d_in[6];
    const float* We1  = (const float*)d_in[7];
    const float* a_e1 = (const float*)d_in[8];
    const float* b1   = (const float*)d_in[9];
    const float* Ws2  = (const float*)d_in[10];
    const float* Wd2  = (const float*)d_in[11];
    const float* a_s2 = (const float*)d_in[12];
    const float* a_d2 = (const float*)d_in[13];
    const float* We2  = (const float*)d_in[14];
    const float* a_e2 = (const float*)d_in[15];
    const float* b2   = (const float*)d_in[16];
    const float* g0   = (const float*)d_in[17];
    const float* be0  = (const float*)d_in[18];
    const float* g1   = (const float*)d_in[19];
    const float* be1  = (const float*)d_in[20];
    float* out = (float*)d_out;

    const int* srcI = ei;
    const int* dstI = ei + NE;

    __half *pH;
    float *pX1, *pP, *pAs, *pAd, *pV1s, *pV1d, *pV2s, *pV2d, *pEaT, *pEaS;
    int *pCntT, *pCntS, *pOffT, *pOffS, *pNbrT, *pEidT, *pNbrS, *pEidS;
    cudaGetSymbolAddress((void**)&pH,   g_H);
    cudaGetSymbolAddress((void**)&pX1,  g_X1);
    cudaGetSymbolAddress((void**)&pP,   g_P);
    cudaGetSymbolAddress((void**)&pAs,  g_as);
    cudaGetSymbolAddress((void**)&pAd,  g_ad);
    cudaGetSymbolAddress((void**)&pV1s, g_V1s);
    cudaGetSymbolAddress((void**)&pV1d, g_V1d);
    cudaGetSymbolAddress((void**)&pV2s, g_V2s);
    cudaGetSymbolAddress((void**)&pV2d, g_V2d);
    cudaGetSymbolAddress((void**)&pCntT, g_cntT);
    cudaGetSymbolAddress((void**)&pCntS, g_cntS);
    cudaGetSymbolAddress((void**)&pOffT, g_offT);
    cudaGetSymbolAddress((void**)&pOffS, g_offS);
    cudaGetSymbolAddress((void**)&pNbrT, g_nbrT);
    cudaGetSymbolAddress((void**)&pEidT, g_eidT);
    cudaGetSymbolAddress((void**)&pNbrS, g_nbrS);
    cudaGetSymbolAddress((void**)&pEidS, g_eidS);
    cudaGetSymbolAddress((void**)&pEaT, g_eaT);
    cudaGetSymbolAddress((void**)&pEaS, g_eaS);

    __half* pHs = pH;
    __half* pHt = pH + (size_t)NS*HC;
    float* pX1t = pX1 + (size_t)NS*HC;

    const dim3 gemmGrid((NALL + 63) / 64, 3);
    const int nodeWarpBlocks = (NS * 32 + 255) / 256;
    const int projBlocks = 592;
    const int zeroBlocks = (NT + NS + 255) / 256;

    // cnt arrays are zero on entry (module-load init / trailing zero_cnt of previous call).
    hist_prep_kernel<<<EDGE_BLOCKS + PREP_BLOCKS, 256>>>(srcI, dstI,
        W1, a_s1, a_d1, Ws2, Wd2, a_s2, a_d2, We1, a_e1, We2, a_e2);
    scan_kernel<<<2, 1024>>>();
    fill_kernel<<<EDGE_BLOCKS, 256>>>(srcI, dstI, ea);
    gemm_fp16_kernel<DIN, DIN><<<gemmGrid, 128>>>(x_s, x_t, NS, W1, pH, NALL);
    proj_kernel<DIN><<<projBlocks, 256>>>(x_s, x_t, NS, pV1s, pV1d, pAs, pAd, NALL);

    agg_kernel<true><<<nodeWarpBlocks, 256>>>(pOffT, pCntT, pNbrT, pEidT, pEaT,
                                              pAs, pAd + (size_t)NS*4, 0, pHs, pP,
                                              b1, g0, be0, pX1t, nullptr, NT);
    agg_kernel<true><<<nodeWarpBlocks, 256>>>(pOffS, pCntS, pNbrS, pEidS, pEaS,
                                              pAs + (size_t)NS*4, pAd, 0, pHt, pP,
                                              b1, g0, be0, pX1, nullptr, NS);

    gemm_fp16_kernel<HC, 96><<<gemmGrid, 128>>>(pX1, pX1t, NALL, Ws2, pH, NALL);
    proj_kernel<HC><<<projBlocks, 256>>>(pX1, pX1t, NALL, pV2s, pV2d, pAs, pAd, NALL);

    agg_kernel<false><<<nodeWarpBlocks, 256>>>(pOffT, pCntT, pNbrT, pEidT, pEaT,
                                               pAs, pAd + (size_t)NS*4, 1, pHs, pP,
                                               b2, g1, be1, out + OFF_XT, out + OFF_ATT, NT);
    agg_kernel<false><<<nodeWarpBlocks, 256>>>(pOffS, pCntS, pNbrS, pEidS, pEaS,
                                               pAs + (size_t)NS*4, pAd, 1, pHt, pP,
                                               b2, g1, be1, out + OFF_XS, out + OFF_ATS, NS);

    zero_cnt_kernel<<<zeroBlocks, 256>>>();
}